// round 1
// baseline (speedup 1.0000x reference)
#include <cuda_runtime.h>
#include <cstdint>

#define BB   8
#define CC   256
#define HH   128
#define WW   128
#define HW   (HH * WW)          // 16384
#define KK   1280
#define PADP 2
#define PP   25                  // 5x5 window

// ---------------- scratch (device globals; no allocations allowed) ----------------
__device__ float g_soft[BB * HW];                         // softmax map
__device__ int   g_coords[BB * KK * 2];                   // clamped (cy,cx)
__device__ float g_nhwc[(size_t)BB * HW * CC];            // 128 MB NHWC feature map

// ---------------- kernel 1: softmax (one block per batch) ----------------
__global__ void softmax_kernel(const float* __restrict__ sal,
                               const float* __restrict__ mask,
                               float* __restrict__ calib_out,
                               float* __restrict__ offs_out) {
    int b = blockIdx.x, tid = threadIdx.x;
    __shared__ float red[32];
    __shared__ float s_bcast;

    float x[16];
    float mx = -3.4e38f;
#pragma unroll
    for (int i = 0; i < 16; i++) {
        int idx = tid + i * 1024;
        float l = (sal[b * HW + idx] + mask[idx]) * 2.0f;   // logits / TEMP(0.5)
        x[i] = l;
        mx = fmaxf(mx, l);
    }
#pragma unroll
    for (int o = 16; o; o >>= 1) mx = fmaxf(mx, __shfl_xor_sync(0xffffffffu, mx, o));
    if ((tid & 31) == 0) red[tid >> 5] = mx;
    __syncthreads();
    if (tid < 32) {
        float vv = red[tid];
#pragma unroll
        for (int o = 16; o; o >>= 1) vv = fmaxf(vv, __shfl_xor_sync(0xffffffffu, vv, o));
        if (tid == 0) s_bcast = vv;
    }
    __syncthreads();
    mx = s_bcast;

    float e[16];
    float se = 0.f;
#pragma unroll
    for (int i = 0; i < 16; i++) { e[i] = expf(x[i] - mx); se += e[i]; }
#pragma unroll
    for (int o = 16; o; o >>= 1) se += __shfl_xor_sync(0xffffffffu, se, o);
    __syncthreads();                       // protect red/s_bcast reuse
    if ((tid & 31) == 0) red[tid >> 5] = se;
    __syncthreads();
    if (tid < 32) {
        float vv = red[tid];
#pragma unroll
        for (int o = 16; o; o >>= 1) vv += __shfl_xor_sync(0xffffffffu, vv, o);
        if (tid == 0) s_bcast = vv;
    }
    __syncthreads();
    float sum = s_bcast;

#pragma unroll
    for (int i = 0; i < 16; i++) {
        int idx = tid + i * 1024;
        float so = e[i] / sum;
        g_soft[b * HW + idx] = so;
        if (calib_out) calib_out[b * HW + idx] = so;
    }

    // offsets output [1,1,P,2] (tiny), written once from block 0
    if (b == 0 && offs_out != nullptr && tid < PP * 2) {
        int p = tid >> 1;
        int comp = tid & 1;
        int gy = p / 5 - PADP;
        int gx = p % 5 - PADP;
        offs_out[tid] = (float)(comp ? gx : gy);
    }
}

// ---------------- kernel 2: full bitonic sort -> top-K (one block per batch) ------
// Sorted descending by soft value, ties broken by lower index (matches jax top_k).
__global__ void sort_topk_kernel(float* __restrict__ coords_out) {
    extern __shared__ char smem[];
    float* v  = (float*)smem;
    int*   id = (int*)(smem + HW * sizeof(float));
    int b = blockIdx.x, tid = threadIdx.x;

    for (int i = tid; i < HW; i += blockDim.x) { v[i] = g_soft[b * HW + i]; id[i] = i; }
    __syncthreads();

    for (int k2 = 2; k2 <= HW; k2 <<= 1) {
        for (int j = k2 >> 1; j > 0; j >>= 1) {
            for (int i = tid; i < HW; i += blockDim.x) {
                int ixj = i ^ j;
                if (ixj > i) {
                    float va = v[i], vb = v[ixj];
                    int   ia = id[i], ib = id[ixj];
                    // "x before y" == (x.v > y.v) || (x.v==y.v && x.i < y.i)
                    bool bBeforeA = (vb > va) || (vb == va && ib < ia);
                    bool aBeforeB = (va > vb) || (va == vb && ia < ib);
                    bool doSwap = ((i & k2) == 0) ? bBeforeA : aBeforeB;
                    if (doSwap) { v[i] = vb; v[ixj] = va; id[i] = ib; id[ixj] = ia; }
                }
            }
            __syncthreads();
        }
    }

    for (int t = tid; t < KK; t += blockDim.x) {
        int src = id[t];
        int cy = src / WW, cx = src % WW;
        cy = min(max(cy, PADP), HH - 1 - PADP);
        cx = min(max(cx, PADP), WW - 1 - PADP);
        g_coords[(b * KK + t) * 2 + 0] = cy;
        g_coords[(b * KK + t) * 2 + 1] = cx;
        if (coords_out) {
            coords_out[(b * KK + t) * 2 + 0] = (float)cy;
            coords_out[(b * KK + t) * 2 + 1] = (float)cx;
        }
    }
}

// ---------------- kernel 3: NCHW -> NHWC transpose (smem tiled) ----------------
__global__ void transpose_kernel(const float* __restrict__ feat) {
    __shared__ float tile[32][33];
    int b   = blockIdx.z;
    int hw0 = blockIdx.x * 32;
    int c0  = blockIdx.y * 32;
    const float* src = feat + (size_t)b * CC * HW;
    float*       dst = g_nhwc + (size_t)b * HW * CC;
    int tx = threadIdx.x, ty = threadIdx.y;
#pragma unroll
    for (int i = 0; i < 32; i += 8)
        tile[ty + i][tx] = src[(size_t)(c0 + ty + i) * HW + hw0 + tx];
    __syncthreads();
#pragma unroll
    for (int i = 0; i < 32; i += 8)
        dst[(size_t)(hw0 + ty + i) * CC + c0 + tx] = tile[tx][ty + i];
}

// ---------------- kernel 4: window gather + mask * distance-weight ----------------
// One block per (b,k) window: 25 pixels x 256 channels = 6400 f32 out.
__global__ void gather_kernel(const float* __restrict__ gamma,
                              float* __restrict__ patches) {
    int bk = blockIdx.x;
    int b = bk / KK;
    int tid = threadIdx.x;

    __shared__ float s_sc[PP];
    __shared__ float s_w[PP];
    __shared__ int   s_pix4[PP];   // float4 base index into g_nhwc
    __shared__ float s_mean;

    int cy = g_coords[bk * 2 + 0];
    int cx = g_coords[bk * 2 + 1];

    if (tid < PP) {
        int gy = tid / 5 - PADP;
        int gx = tid % 5 - PADP;
        int y = cy + gy, xx = cx + gx;         // always in-range (centers clamped)
        int pix = b * HW + y * WW + xx;
        s_pix4[tid] = pix * (CC / 4);
        s_sc[tid] = g_soft[pix];
    }
    __syncthreads();
    if (tid == 0) {
        float sum = 0.f;
#pragma unroll
        for (int p = 0; p < PP; p++) sum += s_sc[p];
        s_mean = sum / 25.0f;
    }
    __syncthreads();
    if (tid < PP) {
        int gy = tid / 5 - PADP;
        int gx = tid % 5 - PADP;
        // clip is a no-op -> pts-center == offsets -> constant distance weight
        float dw = expf(-sqrtf((float)(gy * gy + gx * gx)) * (1.0f / 2.5f));
        float z = gamma[0] * (s_sc[tid] - s_mean);
        float m = 1.0f / (1.0f + expf(-z));
        s_w[tid] = m * dw;
    }
    __syncthreads();

    const float4* src4 = (const float4*)g_nhwc;
    float4* out4 = (float4*)patches + (size_t)bk * (PP * CC / 4);
#pragma unroll
    for (int it = 0; it < 7; it++) {
        int idx = it * 256 + tid;
        if (idx < PP * CC / 4) {
            int p  = idx >> 6;       // 64 float4 per pixel
            int c4 = idx & 63;
            float4 vv = src4[s_pix4[p] + c4];
            float w = s_w[p];
            vv.x *= w; vv.y *= w; vv.z *= w; vv.w *= w;
            out4[idx] = vv;
        }
    }
}

// ---------------- launch ----------------
extern "C" void kernel_launch(void* const* d_in, const int* in_sizes, int n_in,
                              void* d_out, int out_size) {
    const float* feat  = (const float*)d_in[0];
    const float* sal   = (const float*)d_in[1];
    const float* mask  = (const float*)d_in[2];
    const float* gamma = (const float*)d_in[3];
    float* out = (float*)d_out;

    const long long PATCH_N = (long long)BB * KK * PP * CC;   // 65,536,000
    const long long COORD_N = (long long)BB * KK * 2;         // 20,480
    const long long OFF_N   = PP * 2;                         // 50
    const long long CAL_N   = (long long)BB * HW;             // 131,072

    float* patches   = out;
    float* coords_out = nullptr;
    float* offs_out   = nullptr;
    float* calib_out  = nullptr;
    if ((long long)out_size >= PATCH_N + COORD_N + OFF_N + CAL_N) {
        coords_out = out + PATCH_N;
        offs_out   = coords_out + COORD_N;
        calib_out  = offs_out + OFF_N;
    }

    cudaFuncSetAttribute(sort_topk_kernel,
                         cudaFuncAttributeMaxDynamicSharedMemorySize,
                         HW * (int)(sizeof(float) + sizeof(int)));

    softmax_kernel<<<BB, 1024>>>(sal, mask, calib_out, offs_out);
    sort_topk_kernel<<<BB, 1024, HW * (sizeof(float) + sizeof(int))>>>(coords_out);
    transpose_kernel<<<dim3(HW / 32, CC / 32, BB), dim3(32, 8)>>>(feat);
    gather_kernel<<<BB * KK, 256>>>(gamma, patches);
}

// round 2
// speedup vs baseline: 2.2253x; 2.2253x over previous
#include <cuda_runtime.h>
#include <cstdint>

#define BB   8
#define CC   256
#define HH   128
#define WW   128
#define HW   (HH * WW)          // 16384
#define KK   1280
#define PADP 2
#define PP   25                  // 5x5 window

typedef unsigned int  u32;
typedef unsigned long long u64;

// ---------------- scratch (device globals; no allocations allowed) ----------------
__device__ float g_soft[BB * HW];                         // softmax map
__device__ int   g_coords[BB * KK * 2];                   // clamped (cy,cx)
__device__ float g_nhwc[(size_t)BB * HW * CC];            // 128 MB NHWC feature map

// ---------------- kernel 1: softmax (one block per batch) ----------------
__global__ void softmax_kernel(const float* __restrict__ sal,
                               const float* __restrict__ mask,
                               float* __restrict__ calib_out,
                               float* __restrict__ offs_out) {
    int b = blockIdx.x, tid = threadIdx.x;
    __shared__ float red[32];
    __shared__ float s_bcast;

    float x[16];
    float mx = -3.4e38f;
#pragma unroll
    for (int i = 0; i < 16; i++) {
        int idx = tid + i * 1024;
        float l = (sal[b * HW + idx] + mask[idx]) * 2.0f;   // logits / TEMP(0.5)
        x[i] = l;
        mx = fmaxf(mx, l);
    }
#pragma unroll
    for (int o = 16; o; o >>= 1) mx = fmaxf(mx, __shfl_xor_sync(0xffffffffu, mx, o));
    if ((tid & 31) == 0) red[tid >> 5] = mx;
    __syncthreads();
    if (tid < 32) {
        float vv = red[tid];
#pragma unroll
        for (int o = 16; o; o >>= 1) vv = fmaxf(vv, __shfl_xor_sync(0xffffffffu, vv, o));
        if (tid == 0) s_bcast = vv;
    }
    __syncthreads();
    mx = s_bcast;

    float e[16];
    float se = 0.f;
#pragma unroll
    for (int i = 0; i < 16; i++) { e[i] = expf(x[i] - mx); se += e[i]; }
#pragma unroll
    for (int o = 16; o; o >>= 1) se += __shfl_xor_sync(0xffffffffu, se, o);
    __syncthreads();
    if ((tid & 31) == 0) red[tid >> 5] = se;
    __syncthreads();
    if (tid < 32) {
        float vv = red[tid];
#pragma unroll
        for (int o = 16; o; o >>= 1) vv += __shfl_xor_sync(0xffffffffu, vv, o);
        if (tid == 0) s_bcast = vv;
    }
    __syncthreads();
    float sum = s_bcast;

#pragma unroll
    for (int i = 0; i < 16; i++) {
        int idx = tid + i * 1024;
        float so = e[i] / sum;
        g_soft[b * HW + idx] = so;
        if (calib_out) calib_out[b * HW + idx] = so;
    }

    if (b == 0 && offs_out != nullptr && tid < PP * 2) {
        int p = tid >> 1;
        int comp = tid & 1;
        int gy = p / 5 - PADP;
        int gx = p % 5 - PADP;
        offs_out[tid] = (float)(comp ? gx : gy);
    }
}

// ---------------- kernel 2: 2-level radix select + small bitonic sort --------------
// One block (1024 thr) per batch. Keys = float bits of soft (positive -> monotone).
// Exact jax.lax.top_k semantics: value desc, tie -> lower index.
__global__ void topk_select_kernel(float* __restrict__ coords_out) {
    extern __shared__ char smem[];
    u64* cand = (u64*)smem;                                   // 4096 * 8 = 32 KB
    u32* hist = (u32*)(smem + 4096 * sizeof(u64));            // 4096 * 4 = 16 KB
    u32* sbuf = (u32*)(smem + 4096 * sizeof(u64) + 4096 * sizeof(u32)); // 1024*4
    __shared__ u32 s_t1, s_above1, s_t2, s_cnt;

    int b = blockIdx.x, tid = threadIdx.x;
    if (tid == 0) { s_t2 = 0; s_cnt = 0; }

    u32 key[16];
#pragma unroll
    for (int i = 0; i < 16; i++)
        key[i] = __float_as_uint(g_soft[b * HW + i * 1024 + tid]);

    // ---- level 1: bins = key >> 20 (fits in [0,1024) since soft < 1) ----
    hist[tid] = 0;
    __syncthreads();
#pragma unroll
    for (int i = 0; i < 16; i++) atomicAdd(&hist[key[i] >> 20], 1u);
    __syncthreads();

    sbuf[tid] = hist[tid];
    __syncthreads();
    for (int st = 1; st < 1024; st <<= 1) {
        u32 v = sbuf[tid] + ((tid + st < 1024) ? sbuf[tid + st] : 0u);
        __syncthreads();
        sbuf[tid] = v;
        __syncthreads();
    }
    {
        u32 sfx = sbuf[tid];
        u32 nxt = (tid < 1023) ? sbuf[tid + 1] : 0u;
        if (sfx >= KK && nxt < KK) { s_t1 = (u32)tid; s_above1 = nxt; }
    }
    __syncthreads();
    u32 t1 = s_t1;
    u32 Kr = KK - s_above1;           // remaining needed from bin t1

    // ---- level 2: bins = (key >> 8) & 0xFFF within bin t1 ----
    hist[tid] = 0; hist[tid + 1024] = 0; hist[tid + 2048] = 0; hist[tid + 3072] = 0;
    __syncthreads();
#pragma unroll
    for (int i = 0; i < 16; i++)
        if ((key[i] >> 20) == t1) atomicAdd(&hist[(key[i] >> 8) & 0xFFFu], 1u);
    __syncthreads();

    u32 c0 = hist[4 * tid], c1 = hist[4 * tid + 1], c2 = hist[4 * tid + 2], c3 = hist[4 * tid + 3];
    sbuf[tid] = c0 + c1 + c2 + c3;
    __syncthreads();
    for (int st = 1; st < 1024; st <<= 1) {
        u32 v = sbuf[tid] + ((tid + st < 1024) ? sbuf[tid + st] : 0u);
        __syncthreads();
        sbuf[tid] = v;
        __syncthreads();
    }
    {
        u32 G = (tid < 1023) ? sbuf[tid + 1] : 0u;
        u32 sfx3 = G + c3;
        u32 sfx2 = sfx3 + c2;
        u32 sfx1 = sfx2 + c1;
        u32 sfx0 = sfx1 + c0;
        int best = -1;
        if (sfx3 >= Kr)      best = 4 * tid + 3;
        else if (sfx2 >= Kr) best = 4 * tid + 2;
        else if (sfx1 >= Kr) best = 4 * tid + 1;
        else if (sfx0 >= Kr) best = 4 * tid;
        if (best >= 0) atomicMax(&s_t2, (u32)best);
    }
    __syncthreads();
    u32 thr = (t1 << 12) | s_t2;      // accept iff (key >> 8) >= thr

    // ---- compaction ----
#pragma unroll
    for (int i = 0; i < 16; i++) {
        u32 k = key[i];
        if ((k >> 8) >= thr) {
            u32 pos = atomicAdd(&s_cnt, 1u);
            if (pos < 4096) {
                u32 idx = (u32)(i * 1024 + tid);
                cand[pos] = ((u64)k << 32) | (u32)(~idx);
            }
        }
    }
    __syncthreads();
    u32 cnt = s_cnt;
    for (int i = tid; i < 4096; i += 1024)
        if ((u32)i >= cnt) cand[i] = 0ull;
    __syncthreads();

    // ---- bitonic sort 4096 descending ----
    for (u32 k2 = 2; k2 <= 4096; k2 <<= 1) {
        for (u32 j = k2 >> 1; j > 0; j >>= 1) {
#pragma unroll
            for (int r = 0; r < 4; r++) {
                u32 i = (u32)tid + r * 1024;
                u32 ixj = i ^ j;
                if (ixj > i) {
                    u64 a = cand[i], bv = cand[ixj];
                    bool desc = ((i & k2) == 0);
                    bool sw = desc ? (bv > a) : (a > bv);
                    if (sw) { cand[i] = bv; cand[ixj] = a; }
                }
            }
            __syncthreads();
        }
    }

    // ---- emit top-K coords ----
    for (int t = tid; t < KK; t += 1024) {
        u32 idx = ~(u32)cand[t];
        int cy = (int)(idx / WW), cx = (int)(idx % WW);
        cy = min(max(cy, PADP), HH - 1 - PADP);
        cx = min(max(cx, PADP), WW - 1 - PADP);
        g_coords[(b * KK + t) * 2 + 0] = cy;
        g_coords[(b * KK + t) * 2 + 1] = cx;
        if (coords_out) {
            coords_out[(b * KK + t) * 2 + 0] = (float)cy;
            coords_out[(b * KK + t) * 2 + 1] = (float)cx;
        }
    }
}

// ---------------- kernel 3: NCHW -> NHWC transpose (smem tiled) ----------------
__global__ void transpose_kernel(const float* __restrict__ feat) {
    __shared__ float tile[32][33];
    int b   = blockIdx.z;
    int hw0 = blockIdx.x * 32;
    int c0  = blockIdx.y * 32;
    const float* src = feat + (size_t)b * CC * HW;
    float*       dst = g_nhwc + (size_t)b * HW * CC;
    int tx = threadIdx.x, ty = threadIdx.y;
#pragma unroll
    for (int i = 0; i < 32; i += 8)
        tile[ty + i][tx] = src[(size_t)(c0 + ty + i) * HW + hw0 + tx];
    __syncthreads();
#pragma unroll
    for (int i = 0; i < 32; i += 8)
        dst[(size_t)(hw0 + ty + i) * CC + c0 + tx] = tile[tx][ty + i];
}

// ---------------- kernel 4: window gather + mask * distance-weight ----------------
// One block (320 thr) per (b,k) window: 25 pixels x 256 channels, 1600 float4 out.
__global__ void gather_kernel(const float* __restrict__ gamma,
                              float* __restrict__ patches) {
    int bk = blockIdx.x;
    int b = bk / KK;
    int tid = threadIdx.x;

    __shared__ float s_sc[PP];
    __shared__ float s_w[PP];
    __shared__ int   s_pix4[PP];
    __shared__ float s_mean;

    int cy = g_coords[bk * 2 + 0];
    int cx = g_coords[bk * 2 + 1];

    if (tid < PP) {
        int gy = tid / 5 - PADP;
        int gx = tid % 5 - PADP;
        int y = cy + gy, xx = cx + gx;          // in-range: centers clamped
        int pix = b * HW + y * WW + xx;
        s_pix4[tid] = pix * (CC / 4);
        s_sc[tid] = g_soft[pix];
    }
    __syncthreads();
    if (tid == 0) {
        float sum = 0.f;
#pragma unroll
        for (int p = 0; p < PP; p++) sum += s_sc[p];
        s_mean = sum / 25.0f;
    }
    __syncthreads();
    if (tid < PP) {
        int gy = tid / 5 - PADP;
        int gx = tid % 5 - PADP;
        float dw = expf(-sqrtf((float)(gy * gy + gx * gx)) * (1.0f / 2.5f));
        float z = gamma[0] * (s_sc[tid] - s_mean);
        float m = 1.0f / (1.0f + expf(-z));
        s_w[tid] = m * dw;
    }
    __syncthreads();

    const float4* src4 = (const float4*)g_nhwc;
    float4* out4 = (float4*)patches + (size_t)bk * (PP * CC / 4);
#pragma unroll
    for (int it = 0; it < 5; it++) {
        int idx = it * 320 + tid;
        int p  = idx >> 6;         // 64 float4 per pixel
        int c4 = idx & 63;
        float4 vv = src4[s_pix4[p] + c4];
        float w = s_w[p];
        vv.x *= w; vv.y *= w; vv.z *= w; vv.w *= w;
        out4[idx] = vv;
    }
}

// ---------------- launch ----------------
extern "C" void kernel_launch(void* const* d_in, const int* in_sizes, int n_in,
                              void* d_out, int out_size) {
    const float* feat  = (const float*)d_in[0];
    const float* sal   = (const float*)d_in[1];
    const float* mask  = (const float*)d_in[2];
    const float* gamma = (const float*)d_in[3];
    float* out = (float*)d_out;

    const long long PATCH_N = (long long)BB * KK * PP * CC;   // 65,536,000
    const long long COORD_N = (long long)BB * KK * 2;         // 20,480
    const long long OFF_N   = PP * 2;                         // 50
    const long long CAL_N   = (long long)BB * HW;             // 131,072

    float* patches    = out;
    float* coords_out = nullptr;
    float* offs_out   = nullptr;
    float* calib_out  = nullptr;
    if ((long long)out_size >= PATCH_N + COORD_N + OFF_N + CAL_N) {
        coords_out = out + PATCH_N;
        offs_out   = coords_out + COORD_N;
        calib_out  = offs_out + OFF_N;
    }

    const int TOPK_SMEM = 4096 * 8 + 4096 * 4 + 1024 * 4;   // 53,248 B
    cudaFuncSetAttribute(topk_select_kernel,
                         cudaFuncAttributeMaxDynamicSharedMemorySize, TOPK_SMEM);

    transpose_kernel<<<dim3(HW / 32, CC / 32, BB), dim3(32, 8)>>>(feat);
    softmax_kernel<<<BB, 1024>>>(sal, mask, calib_out, offs_out);
    topk_select_kernel<<<BB, 1024, TOPK_SMEM>>>(coords_out);
    gather_kernel<<<BB * KK, 320>>>(gamma, patches);
}

// round 4
// speedup vs baseline: 2.3415x; 1.0522x over previous
#include <cuda_runtime.h>
#include <cstdint>

#define BB   8
#define CC   256
#define HH   128
#define WW   128
#define HW   (HH * WW)          // 16384
#define KK   1280
#define PADP 2
#define PP   25                  // 5x5 window
#define RCAP 56                  // max refs per pixel (absolute bound 49)

typedef unsigned int  u32;
typedef unsigned long long u64;

// ---------------- scratch (device globals; no allocations allowed) ----------------
__device__ float g_soft[BB * HW];                    // softmax map
__device__ int   g_coords[BB * KK * 2];              // clamped (cy,cx), sorted by rank
__device__ u64   g_cand[BB * 4096];                  // threshold-passing candidates
__device__ u32   g_cnt[BB];                          // candidate counts
__device__ float g_wt[BB * KK * PP];                 // per (window,pixel) weight
__device__ u32   g_refcnt[BB * HW];                  // refs per pixel
__device__ u32   g_reflist[(size_t)BB * HW * RCAP];  // packed (k<<5)|p

// ---------------- kernel 1: softmax (+ zero refcnt, + offsets out) ----------------
__global__ void softmax_kernel(const float* __restrict__ sal,
                               const float* __restrict__ mask,
                               float* __restrict__ calib_out,
                               float* __restrict__ offs_out) {
    int b = blockIdx.x, tid = threadIdx.x;
    __shared__ float red[32];
    __shared__ float s_bcast;

    // zero this batch's refcnt (consumed by winprep/scatter later in the chain)
#pragma unroll
    for (int i = 0; i < 16; i++) g_refcnt[b * HW + i * 1024 + tid] = 0;

    float x[16];
    float mx = -3.4e38f;
#pragma unroll
    for (int i = 0; i < 16; i++) {
        int idx = tid + i * 1024;
        float l = (sal[b * HW + idx] + mask[idx]) * 2.0f;   // logits / TEMP(0.5)
        x[i] = l;
        mx = fmaxf(mx, l);
    }
#pragma unroll
    for (int o = 16; o; o >>= 1) mx = fmaxf(mx, __shfl_xor_sync(0xffffffffu, mx, o));
    if ((tid & 31) == 0) red[tid >> 5] = mx;
    __syncthreads();
    if (tid < 32) {
        float vv = red[tid];
#pragma unroll
        for (int o = 16; o; o >>= 1) vv = fmaxf(vv, __shfl_xor_sync(0xffffffffu, vv, o));
        if (tid == 0) s_bcast = vv;
    }
    __syncthreads();
    mx = s_bcast;

    float e[16];
    float se = 0.f;
#pragma unroll
    for (int i = 0; i < 16; i++) { e[i] = expf(x[i] - mx); se += e[i]; }
#pragma unroll
    for (int o = 16; o; o >>= 1) se += __shfl_xor_sync(0xffffffffu, se, o);
    __syncthreads();
    if ((tid & 31) == 0) red[tid >> 5] = se;
    __syncthreads();
    if (tid < 32) {
        float vv = red[tid];
#pragma unroll
        for (int o = 16; o; o >>= 1) vv += __shfl_xor_sync(0xffffffffu, vv, o);
        if (tid == 0) s_bcast = vv;
    }
    __syncthreads();
    float sum = s_bcast;

#pragma unroll
    for (int i = 0; i < 16; i++) {
        int idx = tid + i * 1024;
        float so = e[i] / sum;
        g_soft[b * HW + idx] = so;
        if (calib_out) calib_out[b * HW + idx] = so;
    }

    if (b == 0 && offs_out != nullptr && tid < PP * 2) {
        int p = tid >> 1;
        int comp = tid & 1;
        int gy = p / 5 - PADP;
        int gx = p % 5 - PADP;
        offs_out[tid] = (float)(comp ? gx : gy);
    }
}

// ---------------- kernel 2: 2-level radix threshold + compact to global ----------
__global__ void compact_kernel() {
    extern __shared__ char smem[];
    u32* hist = (u32*)smem;                        // 4096 * 4
    u32* sbuf = (u32*)(smem + 4096 * sizeof(u32)); // 1024 * 4
    __shared__ u32 s_t1, s_above1, s_t2, s_cnt;

    int b = blockIdx.x, tid = threadIdx.x;
    if (tid == 0) { s_t2 = 0; s_cnt = 0; }

    u32 key[16];
#pragma unroll
    for (int i = 0; i < 16; i++)
        key[i] = __float_as_uint(g_soft[b * HW + i * 1024 + tid]);

    // level 1: bins = key >> 20 (soft in (0,1) -> fits [0,1024))
    hist[tid] = 0;
    __syncthreads();
#pragma unroll
    for (int i = 0; i < 16; i++) atomicAdd(&hist[key[i] >> 20], 1u);
    __syncthreads();

    sbuf[tid] = hist[tid];
    __syncthreads();
    for (int st = 1; st < 1024; st <<= 1) {
        u32 v = sbuf[tid] + ((tid + st < 1024) ? sbuf[tid + st] : 0u);
        __syncthreads();
        sbuf[tid] = v;
        __syncthreads();
    }
    {
        u32 sfx = sbuf[tid];
        u32 nxt = (tid < 1023) ? sbuf[tid + 1] : 0u;
        if (sfx >= KK && nxt < KK) { s_t1 = (u32)tid; s_above1 = nxt; }
    }
    __syncthreads();
    u32 t1 = s_t1;
    u32 Kr = KK - s_above1;

    // level 2: bins = (key >> 8) & 0xFFF within bin t1
    hist[tid] = 0; hist[tid + 1024] = 0; hist[tid + 2048] = 0; hist[tid + 3072] = 0;
    __syncthreads();
#pragma unroll
    for (int i = 0; i < 16; i++)
        if ((key[i] >> 20) == t1) atomicAdd(&hist[(key[i] >> 8) & 0xFFFu], 1u);
    __syncthreads();

    u32 c0 = hist[4 * tid], c1 = hist[4 * tid + 1], c2 = hist[4 * tid + 2], c3 = hist[4 * tid + 3];
    sbuf[tid] = c0 + c1 + c2 + c3;
    __syncthreads();
    for (int st = 1; st < 1024; st <<= 1) {
        u32 v = sbuf[tid] + ((tid + st < 1024) ? sbuf[tid + st] : 0u);
        __syncthreads();
        sbuf[tid] = v;
        __syncthreads();
    }
    {
        u32 G = (tid < 1023) ? sbuf[tid + 1] : 0u;
        u32 sfx3 = G + c3;
        u32 sfx2 = sfx3 + c2;
        u32 sfx1 = sfx2 + c1;
        u32 sfx0 = sfx1 + c0;
        int best = -1;
        if (sfx3 >= Kr)      best = 4 * tid + 3;
        else if (sfx2 >= Kr) best = 4 * tid + 2;
        else if (sfx1 >= Kr) best = 4 * tid + 1;
        else if (sfx0 >= Kr) best = 4 * tid;
        if (best >= 0) atomicMax(&s_t2, (u32)best);
    }
    __syncthreads();
    u32 thr = (t1 << 12) | s_t2;

    // compact candidates to global
#pragma unroll
    for (int i = 0; i < 16; i++) {
        u32 k = key[i];
        if ((k >> 8) >= thr) {
            u32 pos = atomicAdd(&s_cnt, 1u);
            if (pos < 4096) {
                u32 idx = (u32)(i * 1024 + tid);
                g_cand[b * 4096 + pos] = ((u64)k << 32) | (u32)(~idx);
            }
        }
    }
    __syncthreads();
    if (tid == 0) g_cnt[b] = min(s_cnt, 4096u);
}

// ---------------- kernel 3: brute-force exact ranking, chip-wide -----------------
// rank_i = #{j : cand_j > cand_i}; unique (idx tie-break baked into low bits).
__global__ void rank_kernel(float* __restrict__ coords_out) {
    __shared__ u64 ch[2048];
    int b = blockIdx.x;
    int tid = threadIdx.x;
    int i = blockIdx.y * 256 + tid;
    u32 cnt = g_cnt[b];

    u64 mine = (i < (int)cnt) ? g_cand[b * 4096 + i] : 0ull;
    u32 rank = 0;
    for (u32 j0 = 0; j0 < cnt; j0 += 2048) {
        u32 m = min(2048u, cnt - j0);
        for (u32 jj = tid; jj < m; jj += 256) ch[jj] = g_cand[b * 4096 + j0 + jj];
        __syncthreads();
        if (i < (int)cnt) {
            u32 jj = 0;
            for (; jj + 4 <= m; jj += 4) {
                rank += (ch[jj] > mine) + (ch[jj + 1] > mine)
                      + (ch[jj + 2] > mine) + (ch[jj + 3] > mine);
            }
            for (; jj < m; jj++) rank += (ch[jj] > mine);
        }
        __syncthreads();
    }
    if (i < (int)cnt && rank < KK) {
        u32 idx = ~(u32)mine;
        int cy = (int)(idx / WW), cx = (int)(idx % WW);
        cy = min(max(cy, PADP), HH - 1 - PADP);
        cx = min(max(cx, PADP), WW - 1 - PADP);
        g_coords[(b * KK + rank) * 2 + 0] = cy;
        g_coords[(b * KK + rank) * 2 + 1] = cx;
        if (coords_out) {
            coords_out[(b * KK + rank) * 2 + 0] = (float)cy;
            coords_out[(b * KK + rank) * 2 + 1] = (float)cx;
        }
    }
}

// ---------------- kernel 4: per-window weights + pixel->refs reverse map ---------
// One warp per window (4 warps / block).
__global__ void winprep_kernel(const float* __restrict__ gamma) {
    int wid  = threadIdx.x >> 5;
    int lane = threadIdx.x & 31;
    int bk = blockIdx.x * 4 + wid;
    int b = bk / KK, k = bk % KK;

    int cy = g_coords[bk * 2 + 0];
    int cx = g_coords[bk * 2 + 1];

    int gy = lane / 5 - PADP;
    int gx = lane % 5 - PADP;
    int pix = b * HW + (cy + gy) * WW + (cx + gx);
    float sc = (lane < PP) ? g_soft[pix] : 0.f;

    float sum = sc;
#pragma unroll
    for (int o = 16; o; o >>= 1) sum += __shfl_xor_sync(0xffffffffu, sum, o);
    float mean = sum * (1.0f / 25.0f);

    if (lane < PP) {
        float dw = expf(-sqrtf((float)(gy * gy + gx * gx)) * (1.0f / 2.5f));
        float z = gamma[0] * (sc - mean);
        float m = 1.0f / (1.0f + expf(-z));
        g_wt[bk * PP + lane] = m * dw;
        u32 pos = atomicAdd(&g_refcnt[pix], 1u);
        if (pos < RCAP)
            g_reflist[(size_t)pix * RCAP + pos] = ((u32)k << 5) | (u32)lane;
    }
}

// ---------------- kernel 5: fused NCHW read -> weighted scatter to patches -------
// grid (HW/32, CC/32, B), block (32,8). Reads feat coalesced, transposes in smem,
// writes each referenced pixel's 32-channel chunk (128B) to its patch slot.
__global__ void scatter_kernel(const float* __restrict__ feat,
                               float* __restrict__ patches) {
    __shared__ float tile[32][33];
    __shared__ u32 s_cnt[32];
    __shared__ int s_total;

    int b   = blockIdx.z;
    int hw0 = blockIdx.x * 32;
    int c0  = blockIdx.y * 32;
    int tx = threadIdx.x, ty = threadIdx.y;
    int tid = ty * 32 + tx;

    if (tid < 32) s_cnt[tid] = g_refcnt[b * HW + hw0 + tid];
    __syncthreads();
    if (tid == 0) {
        int t = 0;
#pragma unroll
        for (int i = 0; i < 32; i++) t += (int)s_cnt[i];
        s_total = t;
    }
    __syncthreads();
    if (s_total == 0) return;

    const float* src = feat + ((size_t)b * CC + c0) * HW + hw0;
#pragma unroll
    for (int i = 0; i < 32; i += 8)
        tile[ty + i][tx] = src[(size_t)(ty + i) * HW + tx];
    __syncthreads();

    int wrp = ty;       // 8 warps
    int lane = tx;
    for (int px = wrp; px < 32; px += 8) {
        u32 n = min(s_cnt[px], (u32)RCAP);
        size_t rbase = (size_t)(b * HW + hw0 + px) * RCAP;
        for (u32 r = 0; r < n; r++) {
            u32 ref = g_reflist[rbase + r];
            u32 k = ref >> 5, p = ref & 31u;
            float w = g_wt[(b * KK + (int)k) * PP + (int)p];
            float v = tile[lane][px] * w;
            patches[(size_t)((b * KK + (int)k) * PP + (int)p) * CC + c0 + lane] = v;
        }
    }
}

// ---------------- launch ----------------
extern "C" void kernel_launch(void* const* d_in, const int* in_sizes, int n_in,
                              void* d_out, int out_size) {
    const float* feat  = (const float*)d_in[0];
    const float* sal   = (const float*)d_in[1];
    const float* mask  = (const float*)d_in[2];
    const float* gamma = (const float*)d_in[3];
    float* out = (float*)d_out;

    const long long PATCH_N = (long long)BB * KK * PP * CC;   // 65,536,000
    const long long COORD_N = (long long)BB * KK * 2;
    const long long OFF_N   = PP * 2;
    const long long CAL_N   = (long long)BB * HW;

    float* patches    = out;
    float* coords_out = nullptr;
    float* offs_out   = nullptr;
    float* calib_out  = nullptr;
    if ((long long)out_size >= PATCH_N + COORD_N + OFF_N + CAL_N) {
        coords_out = out + PATCH_N;
        offs_out   = coords_out + COORD_N;
        calib_out  = offs_out + OFF_N;
    }

    const int COMPACT_SMEM = 4096 * 4 + 1024 * 4;   // 20 KB
    cudaFuncSetAttribute(compact_kernel,
                         cudaFuncAttributeMaxDynamicSharedMemorySize, COMPACT_SMEM);

    softmax_kernel<<<BB, 1024>>>(sal, mask, calib_out, offs_out);
    compact_kernel<<<BB, 1024, COMPACT_SMEM>>>();
    rank_kernel<<<dim3(BB, 16), 256>>>(coords_out);
    winprep_kernel<<<BB * KK / 4, 128>>>(gamma);
    scatter_kernel<<<dim3(HW / 32, CC / 32, BB), dim3(32, 8)>>>(feat, patches);
}

// round 6
// speedup vs baseline: 3.0968x; 1.3226x over previous
#include <cuda_runtime.h>
#include <cstdint>

#define BB   8
#define CC   256
#define HH   128
#define WW   128
#define HW   (HH * WW)          // 16384
#define KK   1280
#define PADP 2
#define PP   25                  // 5x5 window
#define RCAP 56                  // max refs per pixel (absolute bound 49)
#define MAXREF_BLK 1600          // 32 px * 49 < 1600

typedef unsigned int  u32;
typedef unsigned long long u64;

// ---------------- scratch (device globals; no allocations allowed) ----------------
__device__ float g_soft[BB * HW];                    // softmax map
__device__ int   g_coords[BB * KK * 2];              // clamped (cy,cx) by rank
__device__ u64   g_cand[BB * 4096];                  // threshold-passing candidates
__device__ u32   g_cnt[BB];                          // candidate counts
__device__ u32   g_refcnt[BB * HW];                  // refs per pixel
__device__ u64   g_reflist[(size_t)BB * HW * RCAP];  // (w_bits<<32)|(k<<10)|(p<<5)

// ---------------- kernel 1: softmax (+ zero refcnt, + offsets out) ----------------
__global__ void softmax_kernel(const float* __restrict__ sal,
                               const float* __restrict__ mask,
                               float* __restrict__ calib_out,
                               float* __restrict__ offs_out) {
    int b = blockIdx.x, tid = threadIdx.x;
    __shared__ float red[32];
    __shared__ float s_bcast;

#pragma unroll
    for (int i = 0; i < 16; i++) g_refcnt[b * HW + i * 1024 + tid] = 0;

    float x[16];
    float mx = -3.4e38f;
#pragma unroll
    for (int i = 0; i < 16; i++) {
        int idx = tid + i * 1024;
        float l = (sal[b * HW + idx] + mask[idx]) * 2.0f;   // logits / TEMP(0.5)
        x[i] = l;
        mx = fmaxf(mx, l);
    }
#pragma unroll
    for (int o = 16; o; o >>= 1) mx = fmaxf(mx, __shfl_xor_sync(0xffffffffu, mx, o));
    if ((tid & 31) == 0) red[tid >> 5] = mx;
    __syncthreads();
    if (tid < 32) {
        float vv = red[tid];
#pragma unroll
        for (int o = 16; o; o >>= 1) vv = fmaxf(vv, __shfl_xor_sync(0xffffffffu, vv, o));
        if (tid == 0) s_bcast = vv;
    }
    __syncthreads();
    mx = s_bcast;

    float e[16];
    float se = 0.f;
#pragma unroll
    for (int i = 0; i < 16; i++) { e[i] = expf(x[i] - mx); se += e[i]; }
#pragma unroll
    for (int o = 16; o; o >>= 1) se += __shfl_xor_sync(0xffffffffu, se, o);
    __syncthreads();
    if ((tid & 31) == 0) red[tid >> 5] = se;
    __syncthreads();
    if (tid < 32) {
        float vv = red[tid];
#pragma unroll
        for (int o = 16; o; o >>= 1) vv += __shfl_xor_sync(0xffffffffu, vv, o);
        if (tid == 0) s_bcast = vv;
    }
    __syncthreads();
    float sum = s_bcast;

#pragma unroll
    for (int i = 0; i < 16; i++) {
        int idx = tid + i * 1024;
        float so = e[i] / sum;
        g_soft[b * HW + idx] = so;
        if (calib_out) calib_out[b * HW + idx] = so;
    }

    if (b == 0 && offs_out != nullptr && tid < PP * 2) {
        int p = tid >> 1;
        int comp = tid & 1;
        int gy = p / 5 - PADP;
        int gx = p % 5 - PADP;
        offs_out[tid] = (float)(comp ? gx : gy);
    }
}

// ---------------- kernel 2: 2-level radix threshold + compact to global ----------
__global__ void compact_kernel() {
    extern __shared__ char smem[];
    u32* hist = (u32*)smem;                        // 4096 * 4
    u32* sbuf = (u32*)(smem + 4096 * sizeof(u32)); // 1024 * 4
    __shared__ u32 s_t1, s_above1, s_t2, s_cnt;

    int b = blockIdx.x, tid = threadIdx.x;
    if (tid == 0) { s_t2 = 0; s_cnt = 0; }

    u32 key[16];
#pragma unroll
    for (int i = 0; i < 16; i++)
        key[i] = __float_as_uint(g_soft[b * HW + i * 1024 + tid]);

    hist[tid] = 0;
    __syncthreads();
#pragma unroll
    for (int i = 0; i < 16; i++) atomicAdd(&hist[key[i] >> 20], 1u);
    __syncthreads();

    sbuf[tid] = hist[tid];
    __syncthreads();
    for (int st = 1; st < 1024; st <<= 1) {
        u32 v = sbuf[tid] + ((tid + st < 1024) ? sbuf[tid + st] : 0u);
        __syncthreads();
        sbuf[tid] = v;
        __syncthreads();
    }
    {
        u32 sfx = sbuf[tid];
        u32 nxt = (tid < 1023) ? sbuf[tid + 1] : 0u;
        if (sfx >= KK && nxt < KK) { s_t1 = (u32)tid; s_above1 = nxt; }
    }
    __syncthreads();
    u32 t1 = s_t1;
    u32 Kr = KK - s_above1;

    hist[tid] = 0; hist[tid + 1024] = 0; hist[tid + 2048] = 0; hist[tid + 3072] = 0;
    __syncthreads();
#pragma unroll
    for (int i = 0; i < 16; i++)
        if ((key[i] >> 20) == t1) atomicAdd(&hist[(key[i] >> 8) & 0xFFFu], 1u);
    __syncthreads();

    u32 c0 = hist[4 * tid], c1 = hist[4 * tid + 1], c2 = hist[4 * tid + 2], c3 = hist[4 * tid + 3];
    sbuf[tid] = c0 + c1 + c2 + c3;
    __syncthreads();
    for (int st = 1; st < 1024; st <<= 1) {
        u32 v = sbuf[tid] + ((tid + st < 1024) ? sbuf[tid + st] : 0u);
        __syncthreads();
        sbuf[tid] = v;
        __syncthreads();
    }
    {
        u32 G = (tid < 1023) ? sbuf[tid + 1] : 0u;
        u32 sfx3 = G + c3;
        u32 sfx2 = sfx3 + c2;
        u32 sfx1 = sfx2 + c1;
        u32 sfx0 = sfx1 + c0;
        int best = -1;
        if (sfx3 >= Kr)      best = 4 * tid + 3;
        else if (sfx2 >= Kr) best = 4 * tid + 2;
        else if (sfx1 >= Kr) best = 4 * tid + 1;
        else if (sfx0 >= Kr) best = 4 * tid;
        if (best >= 0) atomicMax(&s_t2, (u32)best);
    }
    __syncthreads();
    u32 thr = (t1 << 12) | s_t2;

#pragma unroll
    for (int i = 0; i < 16; i++) {
        u32 k = key[i];
        if ((k >> 8) >= thr) {
            u32 pos = atomicAdd(&s_cnt, 1u);
            if (pos < 4096) {
                u32 idx = (u32)(i * 1024 + tid);
                g_cand[b * 4096 + pos] = ((u64)k << 32) | (u32)(~idx);
            }
        }
    }
    __syncthreads();
    if (tid == 0) g_cnt[b] = min(s_cnt, 4096u);
}

// ---------------- kernel 3: brute-force exact ranking, chip-wide -----------------
__global__ void rank_kernel(float* __restrict__ coords_out) {
    __shared__ u64 ch[2048];
    int b = blockIdx.x;
    int tid = threadIdx.x;
    int i = blockIdx.y * 256 + tid;
    u32 cnt = g_cnt[b];

    u64 mine = (i < (int)cnt) ? g_cand[b * 4096 + i] : 0ull;
    u32 rank = 0;
    for (u32 j0 = 0; j0 < cnt; j0 += 2048) {
        u32 m = min(2048u, cnt - j0);
        for (u32 jj = tid; jj < m; jj += 256) ch[jj] = g_cand[b * 4096 + j0 + jj];
        __syncthreads();
        if (i < (int)cnt) {
            u32 jj = 0;
            for (; jj + 4 <= m; jj += 4) {
                rank += (ch[jj] > mine) + (ch[jj + 1] > mine)
                      + (ch[jj + 2] > mine) + (ch[jj + 3] > mine);
            }
            for (; jj < m; jj++) rank += (ch[jj] > mine);
        }
        __syncthreads();
    }
    if (i < (int)cnt && rank < KK) {
        u32 idx = ~(u32)mine;
        int cy = (int)(idx / WW), cx = (int)(idx % WW);
        cy = min(max(cy, PADP), HH - 1 - PADP);
        cx = min(max(cx, PADP), WW - 1 - PADP);
        g_coords[(b * KK + rank) * 2 + 0] = cy;
        g_coords[(b * KK + rank) * 2 + 1] = cx;
        if (coords_out) {
            coords_out[(b * KK + rank) * 2 + 0] = (float)cy;
            coords_out[(b * KK + rank) * 2 + 1] = (float)cx;
        }
    }
}

// ---------------- kernel 4: weights fused into pixel->refs reverse map -----------
// One warp per window. Ref entry u64 = weight_bits<<32 | k<<10 | p<<5 (px added later).
__global__ void winprep_kernel(const float* __restrict__ gamma) {
    int wid  = threadIdx.x >> 5;
    int lane = threadIdx.x & 31;
    int bk = blockIdx.x * 4 + wid;
    int b = bk / KK, k = bk % KK;

    int cy = g_coords[bk * 2 + 0];
    int cx = g_coords[bk * 2 + 1];

    int gy = lane / 5 - PADP;
    int gx = lane % 5 - PADP;
    int pix = b * HW + (cy + gy) * WW + (cx + gx);
    float sc = (lane < PP) ? g_soft[pix] : 0.f;

    float sum = sc;
#pragma unroll
    for (int o = 16; o; o >>= 1) sum += __shfl_xor_sync(0xffffffffu, sum, o);
    float mean = sum * (1.0f / 25.0f);

    if (lane < PP) {
        float dw = expf(-sqrtf((float)(gy * gy + gx * gx)) * (1.0f / 2.5f));
        float z = gamma[0] * (sc - mean);
        float m = 1.0f / (1.0f + expf(-z));
        u64 entry = ((u64)__float_as_uint(m * dw) << 32)
                  | ((u32)k << 10) | ((u32)lane << 5);
        u32 pos = atomicAdd(&g_refcnt[pix], 1u);
        if (pos < RCAP)
            g_reflist[(size_t)pix * RCAP + pos] = entry;
    }
}

// ---------------- kernel 5: scatter, 32 px x 256 ch per block ---------------------
// Phase A: counts+prefix. Phase B: stage refs in smem (parallel loads, full MLP).
// Phase C: feat tile [32px][256ch] via conflict-free [32][257]. Phase D: warps
// round-robin over refs; each ref = 8 independent 128B stores (latency-free).
__global__ void scatter_kernel(const float* __restrict__ feat,
                               float* __restrict__ patches) {
    extern __shared__ char smem[];
    float* tile = (float*)smem;                              // [32][257]
    u64*   refs = (u64*)(smem + 32 * 257 * sizeof(float));   // [MAXREF_BLK]
    u32*   s_cnt  = (u32*)((char*)refs + MAXREF_BLK * sizeof(u64)); // [32]
    u32*   s_pref = s_cnt + 32;                              // [33]

    int b   = blockIdx.y;
    int hw0 = blockIdx.x * 32;
    int tid = threadIdx.x;
    int lane = tid & 31, wid = tid >> 5;

    // Phase A: ref counts + prefix
    if (tid < 32) s_cnt[tid] = min(g_refcnt[b * HW + hw0 + tid], (u32)RCAP);
    __syncthreads();
    if (tid < 32) {
        u32 v = s_cnt[tid];
        u32 sc = v;
#pragma unroll
        for (int o = 1; o < 32; o <<= 1) {
            u32 n = __shfl_up_sync(0xffffffffu, sc, o);
            if (lane >= o) sc += n;
        }
        s_pref[tid + 1] = sc;           // inclusive -> exclusive via +1
        if (tid == 0) s_pref[0] = 0;
    }
    __syncthreads();
    int total = (int)s_pref[32];
    if (total == 0) return;

    // Phase B: stage refs (warp w -> px w*4..w*4+3, lanes load slots in parallel)
#pragma unroll
    for (int q = 0; q < 4; q++) {
        int px = wid * 4 + q;
        u32 n = s_cnt[px];
        size_t rbase = (size_t)(b * HW + hw0 + px) * RCAP;
        for (u32 s = lane; s < n; s += 32)
            refs[s_pref[px] + s] = g_reflist[rbase + s] | (u32)px;
    }

    // Phase C: feat tile. thread loads ch = wid + i*8, px = lane (coalesced 128B rows)
    const float* src = feat + (size_t)b * CC * HW + hw0;
#pragma unroll
    for (int i = 0; i < 32; i++) {
        int c = wid + i * 8;
        tile[lane * 257 + c] = src[(size_t)c * HW + lane];
    }
    __syncthreads();

    // Phase D: scatter
    for (int r = wid; r < total; r += 8) {
        u64 e = refs[r];
        int px = (int)(e & 31u);
        int p  = (int)((e >> 5) & 31u);
        int k  = (int)((e >> 10) & 2047u);
        float w = __uint_as_float((u32)(e >> 32));
        float* dst = patches + (size_t)((b * KK + k) * PP + p) * CC;
        const float* trow = tile + px * 257;
#pragma unroll
        for (int i = 0; i < 8; i++) {
            int c = i * 32 + lane;
            dst[c] = trow[c] * w;
        }
    }
}

// ---------------- launch ----------------
extern "C" void kernel_launch(void* const* d_in, const int* in_sizes, int n_in,
                              void* d_out, int out_size) {
    const float* feat  = (const float*)d_in[0];
    const float* sal   = (const float*)d_in[1];
    const float* mask  = (const float*)d_in[2];
    const float* gamma = (const float*)d_in[3];
    float* out = (float*)d_out;

    const long long PATCH_N = (long long)BB * KK * PP * CC;   // 65,536,000
    const long long COORD_N = (long long)BB * KK * 2;
    const long long OFF_N   = PP * 2;
    const long long CAL_N   = (long long)BB * HW;

    float* patches    = out;
    float* coords_out = nullptr;
    float* offs_out   = nullptr;
    float* calib_out  = nullptr;
    if ((long long)out_size >= PATCH_N + COORD_N + OFF_N + CAL_N) {
        coords_out = out + PATCH_N;
        offs_out   = coords_out + COORD_N;
        calib_out  = offs_out + OFF_N;
    }

    const int COMPACT_SMEM = 4096 * 4 + 1024 * 4;   // 20 KB
    cudaFuncSetAttribute(compact_kernel,
                         cudaFuncAttributeMaxDynamicSharedMemorySize, COMPACT_SMEM);

    const int SCATTER_SMEM = 32 * 257 * 4 + MAXREF_BLK * 8 + (32 + 33) * 4; // ~45.9 KB
    cudaFuncSetAttribute(scatter_kernel,
                         cudaFuncAttributeMaxDynamicSharedMemorySize, SCATTER_SMEM);

    softmax_kernel<<<BB, 1024>>>(sal, mask, calib_out, offs_out);
    compact_kernel<<<BB, 1024, COMPACT_SMEM>>>();
    rank_kernel<<<dim3(BB, 16), 256>>>(coords_out);
    winprep_kernel<<<BB * KK / 4, 128>>>(gamma);
    scatter_kernel<<<dim3(HW / 32, BB), 256, SCATTER_SMEM>>>(feat, patches);
}